// round 13
// baseline (speedup 1.0000x reference)
#include <cuda_runtime.h>
#include <cuda_fp16.h>

#define N_NODES 50000
#define N_EDGES 800000
#define NB1 196             // ceil(50000/256)
#define PREP_EDGE_BLOCKS 3125   // 800000/256 exactly

// packed per-destination-node record (64B): sector 0 = scatter's read set,
// sector 1 = esum accumulator (scatter RED target, k_node read)
struct __align__(32) NodeRec {
    float4 adst;   // a_dst per head
    int beg;       // segment start
    int cnt;       // segment length
    int pad0, pad1;
    float4 esum;   // segment sum of exp(leaky(logit)) per head
};

// ---------------- scratch (static device globals; no allocation) ----------------
__device__ __align__(16) int   g_src[N_EDGES];
__device__ __align__(16) int   g_dst[N_EDGES];
__device__ __align__(16) int   g_rank[N_EDGES];
__device__ int   g_cnt[N_NODES];            // invariant: all-zero at kernel_launch entry
__device__ int   g_scan[NB1 * 256];
__device__ int   g_btot[NB1];
__device__ NodeRec g_nd[N_NODES];
__device__ __align__(16) int     g_ssrc[N_EDGES];
__device__ __align__(16) float   g_salpha[N_EDGES * 4];    // exp(leaky(logit)) per head, 12.8 MB
__device__ __align__(16) __half2 g_x2[N_NODES * 128];      // x in fp16, 25.6 MB
__device__ __align__(16) float   g_asrc[N_NODES * 4];
__device__ __align__(16) __half  g_WhT[256 * 64];          // W transposed [n][k], fp16
__device__ float g_v[12];                                  // [edim*4 + head]

// ====== K1: prep (block-local dtype detect + unpack + hist/rank) + W convert + v_edge ======
__global__ void __launch_bounds__(256) k_prep(const unsigned* __restrict__ p,
                                              const float* __restrict__ W,
                                              const float* __restrict__ W_edge,
                                              const float* __restrict__ att_edge) {
    int b = blockIdx.x, t = threadIdx.x;
    if (b < PREP_EDGE_BLOCKS) {
        __shared__ unsigned wacc[8];
        __shared__ int s_is64;
        int e = b * 256 + t;                       // always < N_EDGES (exact tiling)
        unsigned acc = p[2 * e + 1];               // high word if int64
#pragma unroll
        for (int o = 16; o; o >>= 1) acc |= __shfl_xor_sync(0xffffffffu, acc, o);
        if ((t & 31) == 0) wacc[t >> 5] = acc;
        __syncthreads();
        if (t == 0) {
            unsigned a = 0;
#pragma unroll
            for (int i = 0; i < 8; i++) a |= wacc[i];
            s_is64 = (a == 0);
        }
        __syncthreads();
        int s, d;
        if (s_is64) {
            const long long* q = (const long long*)p;
            s = (int)q[e]; d = (int)q[N_EDGES + e];
        } else {
            const int* q = (const int*)p;
            s = q[e]; d = q[N_EDGES + e];
        }
        g_src[e] = s;
        g_dst[e] = d;
        g_rank[e] = atomicAdd(&g_cnt[d], 1);
    } else {
        int wb = b - PREP_EDGE_BLOCKS;
        if (wb < 64) {
            int j = wb * 256 + t;                  // j = n*64 + k
            int n = j >> 6, k = j & 63;
            g_WhT[j] = __float2half(W[k * 256 + n]);
        } else if (t < 192) {
            int pair = t >> 4, l = t & 15;         // pair = d*4 + h
            int d = pair >> 2, hh = pair & 3;
            float s = 0.0f;
#pragma unroll
            for (int q = 0; q < 4; q++)
                s += W_edge[d * 256 + hh * 64 + l + 16 * q] * att_edge[hh * 64 + l + 16 * q];
            s += __shfl_xor_sync(0xffffffffu, s, 8);
            s += __shfl_xor_sync(0xffffffffu, s, 4);
            s += __shfl_xor_sync(0xffffffffu, s, 2);
            s += __shfl_xor_sync(0xffffffffu, s, 1);
            if (l == 0) g_v[pair] = s;
        }
    }
}

// ====== K2: per-block inclusive scan (shuffle-based) ======
__global__ void __launch_bounds__(256) k_scan1() {
    __shared__ int ws[8];
    int b = blockIdx.x, t = threadIdx.x, lane = t & 31, w = t >> 5;
    int i = b * 256 + t;
    int x = (i < N_NODES) ? g_cnt[i] : 0;
#pragma unroll
    for (int o = 1; o < 32; o <<= 1) {
        int u = __shfl_up_sync(0xffffffffu, x, o);
        if (lane >= o) x += u;
    }
    if (lane == 31) ws[w] = x;
    __syncthreads();
    if (t < 8) {
        int y = ws[t];
#pragma unroll
        for (int o = 1; o < 8; o <<= 1) {
            int u = __shfl_up_sync(0x000000ffu, y, o);
            if (t >= o) y += u;
        }
        ws[t] = y;
    }
    __syncthreads();
    if (w) x += ws[w - 1];
    g_scan[i] = x;                       // inclusive within block
    if (t == 255) g_btot[b] = x;
}

// ====== K3: block offsets + write NodeRec.beg/cnt + zero esum + reset g_cnt ======
__global__ void __launch_bounds__(256) k_scanB() {
    __shared__ int ws[8];
    int b = blockIdx.x, t = threadIdx.x, lane = t & 31, w = t >> 5;
    int v = (t < b) ? g_btot[t] : 0;
#pragma unroll
    for (int o = 16; o; o >>= 1) v += __shfl_xor_sync(0xffffffffu, v, o);
    if (lane == 0) ws[w] = v;
    __syncthreads();
    int boff = 0;
#pragma unroll
    for (int k = 0; k < 8; k++) boff += ws[k];
    int i = b * 256 + t;
    if (i < N_NODES) {
        int c = g_cnt[i];
        g_nd[i].beg = g_scan[i] - c + boff;       // exclusive prefix
        g_nd[i].cnt = c;
        g_nd[i].esum = make_float4(0.f, 0.f, 0.f, 0.f);
        g_cnt[i] = 0;                             // restore invariant for next replay
    }
}

// ---------------- tensor-core GEMM x = h @ W, fused a_src/a_dst ----------------
__device__ __forceinline__ void mma16816(float* c, unsigned a0, unsigned a1, unsigned a2,
                                         unsigned a3, unsigned b0, unsigned b1) {
    asm volatile(
        "mma.sync.aligned.m16n8k16.row.col.f32.f16.f16.f32 "
        "{%0,%1,%2,%3},{%4,%5,%6,%7},{%8,%9},{%0,%1,%2,%3};\n"
        : "+f"(c[0]), "+f"(c[1]), "+f"(c[2]), "+f"(c[3])
        : "r"(a0), "r"(a1), "r"(a2), "r"(a3), "r"(b0), "r"(b1));
}

__device__ __forceinline__ void ldsm4(unsigned& r0, unsigned& r1, unsigned& r2, unsigned& r3,
                                      unsigned saddr) {
    asm volatile("ldmatrix.sync.aligned.m8n8.x4.shared.b16 {%0,%1,%2,%3}, [%4];"
                 : "=r"(r0), "=r"(r1), "=r"(r2), "=r"(r3) : "r"(saddr));
}

// 64 nodes/block; 8 warps: rt = w&3 (16-row tile), cg = w>>2 (128-col group = 2 heads)
__global__ void __launch_bounds__(256, 2) k_gemm(const float* __restrict__ h,
                                                 const float* __restrict__ att_src,
                                                 const float* __restrict__ att_dst) {
    __shared__ __half As[64 * 72];    // 9216 B
    __shared__ __half Ws[256 * 72];   // 36864 B; re-used as store-stage after mainloop
    int t = threadIdx.x, lane = t & 31, w = t >> 5;
    int n0 = blockIdx.x * 64;

#pragma unroll
    for (int q = 0; q < 8; q++) {
        int j = t + 256 * q;
        int n = j >> 3, c = j & 7;
        *(uint4*)&Ws[n * 72 + c * 8] = ((const uint4*)g_WhT)[j];
    }
#pragma unroll
    for (int q = 0; q < 4; q++) {
        int i = t + 256 * q;
        int r = i >> 4, c4 = (i & 15) * 4;
        int node = n0 + r;
        float4 hv = (node < N_NODES) ? *(const float4*)&h[node * 64 + c4]
                                     : make_float4(0.f, 0.f, 0.f, 0.f);
        __half2 p0 = __floats2half2_rn(hv.x, hv.y);
        __half2 p1 = __floats2half2_rn(hv.z, hv.w);
        uint2 pk = {*(unsigned*)&p0, *(unsigned*)&p1};
        *(uint2*)&As[r * 72 + c4] = pk;
    }
    __syncthreads();

    int rt = w & 3, cg = w >> 2;
    int rbase = rt * 16;
    int qr = lane >> 2, qc = lane & 3;

    unsigned as_base = (unsigned)__cvta_generic_to_shared(As);
    unsigned ws_base = (unsigned)__cvta_generic_to_shared(Ws);
    unsigned a_addr0 = as_base + ((rbase + (lane & 15)) * 72 + 8 * (lane >> 4)) * 2;
    unsigned b_lane_off = (((lane & 7) + 8 * ((lane >> 3) >> 1)) * 72 + 8 * ((lane >> 3) & 1)) * 2;

    float acc[16][4];
#pragma unroll
    for (int i = 0; i < 16; i++)
#pragma unroll
        for (int j = 0; j < 4; j++) acc[i][j] = 0.f;

#pragma unroll
    for (int ks = 0; ks < 4; ks++) {
        int kk = ks * 16;
        unsigned a0, a1, a2, a3;
        ldsm4(a0, a1, a2, a3, a_addr0 + kk * 2);
#pragma unroll
        for (int nf2 = 0; nf2 < 8; nf2++) {
            int n = cg * 128 + nf2 * 16;
            unsigned b0, b1, b2, b3;
            ldsm4(b0, b1, b2, b3, ws_base + n * 144 + b_lane_off + kk * 2);
            mma16816(acc[nf2 * 2],     a0, a1, a2, a3, b0, b1);
            mma16816(acc[nf2 * 2 + 1], a0, a1, a2, a3, b2, b3);
        }
    }
    __syncthreads();   // all warps done reading Ws — safe to overlay stage

    // ---- stage x (half2) into smem, pitch 132 words: bank = 4*qr+qc, conflict-free ----
    unsigned* stage = (unsigned*)Ws;   // 64 rows * 132 words = 33792 B <= 36864 B
    int node_lo = n0 + rbase + qr;
    int node_hi = node_lo + 8;
    float psA_lo = 0.f, psA_hi = 0.f, pdA_lo = 0.f, pdA_hi = 0.f;   // head cg*2
    float psB_lo = 0.f, psB_hi = 0.f, pdB_lo = 0.f, pdB_hi = 0.f;   // head cg*2+1
#pragma unroll
    for (int nf = 0; nf < 16; nf++) {
        int col = cg * 128 + nf * 8 + 2 * qc;
        float2 sv = *(const float2*)&att_src[col];
        float2 dv = *(const float2*)&att_dst[col];
        if (nf < 8) {
            psA_lo += acc[nf][0] * sv.x + acc[nf][1] * sv.y;
            psA_hi += acc[nf][2] * sv.x + acc[nf][3] * sv.y;
            pdA_lo += acc[nf][0] * dv.x + acc[nf][1] * dv.y;
            pdA_hi += acc[nf][2] * dv.x + acc[nf][3] * dv.y;
        } else {
            psB_lo += acc[nf][0] * sv.x + acc[nf][1] * sv.y;
            psB_hi += acc[nf][2] * sv.x + acc[nf][3] * sv.y;
            pdB_lo += acc[nf][0] * dv.x + acc[nf][1] * dv.y;
            pdB_hi += acc[nf][2] * dv.x + acc[nf][3] * dv.y;
        }
        int h2 = cg * 64 + nf * 4 + qc;   // half2 column index
        __half2 plo = __floats2half2_rn(acc[nf][0], acc[nf][1]);
        __half2 phi = __floats2half2_rn(acc[nf][2], acc[nf][3]);
        stage[(rbase + qr) * 132 + h2]     = *(unsigned*)&plo;
        stage[(rbase + qr + 8) * 132 + h2] = *(unsigned*)&phi;
    }
#pragma unroll
    for (int o = 1; o <= 2; o <<= 1) {
        psA_lo += __shfl_xor_sync(0xffffffffu, psA_lo, o);
        psA_hi += __shfl_xor_sync(0xffffffffu, psA_hi, o);
        pdA_lo += __shfl_xor_sync(0xffffffffu, pdA_lo, o);
        pdA_hi += __shfl_xor_sync(0xffffffffu, pdA_hi, o);
        psB_lo += __shfl_xor_sync(0xffffffffu, psB_lo, o);
        psB_hi += __shfl_xor_sync(0xffffffffu, psB_hi, o);
        pdB_lo += __shfl_xor_sync(0xffffffffu, pdB_lo, o);
        pdB_hi += __shfl_xor_sync(0xffffffffu, pdB_hi, o);
    }
    if (qc == 0) {
        int hA = cg * 2, hB = cg * 2 + 1;
        if (node_lo < N_NODES) {
            g_asrc[node_lo * 4 + hA] = psA_lo;
            g_asrc[node_lo * 4 + hB] = psB_lo;
            ((float*)&g_nd[node_lo].adst)[hA] = pdA_lo;
            ((float*)&g_nd[node_lo].adst)[hB] = pdB_lo;
        }
        if (node_hi < N_NODES) {
            g_asrc[node_hi * 4 + hA] = psA_hi;
            g_asrc[node_hi * 4 + hB] = psB_hi;
            ((float*)&g_nd[node_hi].adst)[hA] = pdA_hi;
            ((float*)&g_nd[node_hi].adst)[hB] = pdB_hi;
        }
    }
    __syncthreads();

    // ---- coalesced copy stage -> g_x2: 2048 uint4, 8 per thread ----
#pragma unroll
    for (int q = 0; q < 8; q++) {
        int idx = t + 256 * q;
        int r = idx >> 5;            // row 0..63
        int c4 = (idx & 31) * 4;     // word col, 16B aligned
        int node = n0 + r;
        if (node < N_NODES)
            ((uint4*)&g_x2[node * 128])[idx & 31] = *(uint4*)&stage[r * 132 + c4];
    }
}

// ------- scatter: store exp(leaky(logit)) + RED esum into NodeRec (no node pass 1) -------
__global__ void k_scatter(const float* __restrict__ attr) {
    int e = blockIdx.x * blockDim.x + threadIdx.x;
    if (e >= N_EDGES) return;
    int s = g_src[e], d = g_dst[e];
    float4 ad = g_nd[d].adst;
    int pos = g_nd[d].beg + g_rank[e];        // same 32B sector as adst
    float a0 = attr[e * 3 + 0], a1 = attr[e * 3 + 1], a2 = attr[e * 3 + 2];
    float4 as = *(const float4*)&g_asrc[s * 4];
    float4 o;
    o.x = as.x + ad.x + a0 * g_v[0] + a1 * g_v[4] + a2 * g_v[8];
    o.y = as.y + ad.y + a0 * g_v[1] + a1 * g_v[5] + a2 * g_v[9];
    o.z = as.z + ad.z + a0 * g_v[2] + a1 * g_v[6] + a2 * g_v[10];
    o.w = as.w + ad.w + a0 * g_v[3] + a1 * g_v[7] + a2 * g_v[11];
    o.x = o.x > 0.f ? o.x : 0.2f * o.x;
    o.y = o.y > 0.f ? o.y : 0.2f * o.y;
    o.z = o.z > 0.f ? o.z : 0.2f * o.z;
    o.w = o.w > 0.f ? o.w : 0.2f * o.w;
    // logits are O(10) here; exp is far from overflow (clamp at 80 for safety)
    o.x = expf(fminf(o.x, 80.f));
    o.y = expf(fminf(o.y, 80.f));
    o.z = expf(fminf(o.z, 80.f));
    o.w = expf(fminf(o.w, 80.f));
    *(float4*)&g_salpha[pos * 4] = o;
    g_ssrc[pos] = s;
    atomicAdd(&g_nd[d].esum, o);              // vector RED, 50k spread addresses
}

// ---------------- warp per node: single gather pass + LN + SiLU ----------------
__global__ void __launch_bounds__(256) k_node(float* __restrict__ out,
                                              const float* __restrict__ bias,
                                              const float* __restrict__ gamma,
                                              const float* __restrict__ beta) {
    int t = threadIdx.x, lane = t & 31, w = t >> 5;
    int n = blockIdx.x * 8 + w;
    int2 seg = *(const int2*)&g_nd[n].beg;
    float4 es = g_nd[n].esum;
    int beg = seg.x, end = seg.x + seg.y;
    const float4* sal = (const float4*)g_salpha;

    // per-lane head constants
    int hd = lane >> 3;
    float sh = (hd == 0) ? es.x : (hd == 1) ? es.y : (hd == 2) ? es.z : es.w;
    float ih = 0.25f / (sh + 1e-16f);

    // single pass: weighted gather of fp16 x (weight = stored exp; normalize at end)
    float acc[8];
#pragma unroll
    for (int i = 0; i < 8; i++) acc[i] = 0.f;
    const uint4* xv4 = (const uint4*)g_x2;
    for (int k = beg; k < end; k++) {
        float4 a = sal[k];
        int s = g_ssrc[k];
        float wgt = (hd == 0) ? a.x : (hd == 1) ? a.y : (hd == 2) ? a.z : a.w;
        uint4 xv = xv4[s * 32 + lane];
        const __half2* hp = (const __half2*)&xv;
#pragma unroll
        for (int i = 0; i < 4; i++) {
            float2 f = __half22float2(hp[i]);
            acc[2 * i]     += wgt * f.x;
            acc[2 * i + 1] += wgt * f.y;
        }
    }
#pragma unroll
    for (int i = 0; i < 8; i++) {
        acc[i] *= ih;                    // normalize before cross-head fold
        acc[i] += __shfl_xor_sync(0xffffffffu, acc[i], 8);
        acc[i] += __shfl_xor_sync(0xffffffffu, acc[i], 16);
    }

    // LN + SiLU over 64 channels (lanes 0..7 write)
    int j = lane & 7;
    float4 b0 = ((const float4*)bias)[2 * j];
    float4 b1 = ((const float4*)bias)[2 * j + 1];
    float v[8] = {acc[0] + b0.x, acc[1] + b0.y, acc[2] + b0.z, acc[3] + b0.w,
                  acc[4] + b1.x, acc[5] + b1.y, acc[6] + b1.z, acc[7] + b1.w};
    float sum = 0.f, sq = 0.f;
#pragma unroll
    for (int i = 0; i < 8; i++) { sum += v[i]; sq += v[i] * v[i]; }
#pragma unroll
    for (int o = 4; o; o >>= 1) {
        sum += __shfl_xor_sync(0xffffffffu, sum, o);
        sq  += __shfl_xor_sync(0xffffffffu, sq, o);
    }
    float mu  = sum * (1.0f / 64.0f);
    float var = sq * (1.0f / 64.0f) - mu * mu;
    float inv = rsqrtf(var + 1e-5f);
    float4 g0 = ((const float4*)gamma)[2 * j];
    float4 g1 = ((const float4*)gamma)[2 * j + 1];
    float4 e0 = ((const float4*)beta)[2 * j];
    float4 e1 = ((const float4*)beta)[2 * j + 1];
    float gg[8] = {g0.x, g0.y, g0.z, g0.w, g1.x, g1.y, g1.z, g1.w};
    float ee[8] = {e0.x, e0.y, e0.z, e0.w, e1.x, e1.y, e1.z, e1.w};
    float y[8];
#pragma unroll
    for (int i = 0; i < 8; i++) {
        float yy = (v[i] - mu) * inv * gg[i] + ee[i];
        y[i] = yy / (1.0f + expf(-yy));
    }
    if (lane < 8) {
        float4 o0 = {y[0], y[1], y[2], y[3]};
        float4 o1 = {y[4], y[5], y[6], y[7]};
        ((float4*)out)[n * 16 + 2 * j]     = o0;
        ((float4*)out)[n * 16 + 2 * j + 1] = o1;
    }
}

extern "C" void kernel_launch(void* const* d_in, const int* in_sizes, int n_in,
                              void* d_out, int out_size) {
    // order: t, h, edge_index, edge_attr, W, att_src, att_dst,
    //        W_edge, att_edge, bias, ln_gamma, ln_beta
    const float* h        = (const float*)d_in[1];
    const void*  ei       = d_in[2];
    const float* attr     = (const float*)d_in[3];
    const float* W        = (const float*)d_in[4];
    const float* att_src  = (const float*)d_in[5];
    const float* att_dst  = (const float*)d_in[6];
    const float* W_edge   = (const float*)d_in[7];
    const float* att_edge = (const float*)d_in[8];
    const float* bias     = (const float*)d_in[9];
    const float* gamma    = (const float*)d_in[10];
    const float* beta     = (const float*)d_in[11];
    float* out = (float*)d_out;

    k_prep   <<<PREP_EDGE_BLOCKS + 65, 256>>>((const unsigned*)ei, W, W_edge, att_edge);
    k_scan1  <<<NB1, 256>>>();
    k_scanB  <<<NB1, 256>>>();
    k_gemm   <<<(N_NODES + 63) / 64, 256>>>(h, att_src, att_dst);
    k_scatter<<<(N_EDGES + 255) / 256, 256>>>(attr);
    k_node   <<<N_NODES / 8, 256>>>(out, bias, gamma, beta);
}

// round 14
// speedup vs baseline: 1.0621x; 1.0621x over previous
#include <cuda_runtime.h>
#include <cuda_fp16.h>

#define N_NODES 50000
#define N_EDGES 800000
#define NB1 196             // ceil(50000/256)
#define PREP_EDGE_BLOCKS 3125   // 800000/256 exactly

// packed per-destination-node record: one 32B sector serves scatter's whole need
struct __align__(32) NodeRec {
    float4 adst;   // a_dst per head
    int beg;       // segment start
    int cnt;       // segment length
    int pad0, pad1;
};

// ---------------- scratch (static device globals; no allocation) ----------------
__device__ __align__(16) int   g_src[N_EDGES];
__device__ __align__(16) int   g_dst[N_EDGES];
__device__ __align__(16) int   g_rank[N_EDGES];
__device__ int   g_cnt[N_NODES];            // invariant: all-zero at kernel_launch entry
__device__ int   g_scan[NB1 * 256];
__device__ int   g_btot[NB1];
__device__ NodeRec g_nd[N_NODES];
__device__ __align__(16) int     g_ssrc[N_EDGES];
__device__ __align__(16) float   g_salpha[N_EDGES * 4];    // exp(leaky(logit)) per head, 12.8 MB
__device__ __align__(16) __half2 g_x2[N_NODES * 128];      // x in fp16, 25.6 MB
__device__ __align__(16) float   g_asrc[N_NODES * 4];
__device__ __align__(16) __half  g_WhT[256 * 64];          // W transposed [n][k], fp16
__device__ float g_v[12];                                  // [edim*4 + head]

// ====== K1: prep (block-local dtype detect + unpack + hist/rank) + W convert + v_edge ======
__global__ void __launch_bounds__(256) k_prep(const unsigned* __restrict__ p,
                                              const float* __restrict__ W,
                                              const float* __restrict__ W_edge,
                                              const float* __restrict__ att_edge) {
    int b = blockIdx.x, t = threadIdx.x;
    if (b < PREP_EDGE_BLOCKS) {
        __shared__ unsigned wacc[8];
        __shared__ int s_is64;
        int e = b * 256 + t;                       // always < N_EDGES (exact tiling)
        unsigned acc = p[2 * e + 1];               // high word if int64
#pragma unroll
        for (int o = 16; o; o >>= 1) acc |= __shfl_xor_sync(0xffffffffu, acc, o);
        if ((t & 31) == 0) wacc[t >> 5] = acc;
        __syncthreads();
        if (t == 0) {
            unsigned a = 0;
#pragma unroll
            for (int i = 0; i < 8; i++) a |= wacc[i];
            s_is64 = (a == 0);
        }
        __syncthreads();
        int s, d;
        if (s_is64) {
            const long long* q = (const long long*)p;
            s = (int)q[e]; d = (int)q[N_EDGES + e];
        } else {
            const int* q = (const int*)p;
            s = q[e]; d = q[N_EDGES + e];
        }
        g_src[e] = s;
        g_dst[e] = d;
        g_rank[e] = atomicAdd(&g_cnt[d], 1);
    } else {
        int wb = b - PREP_EDGE_BLOCKS;
        if (wb < 64) {
            int j = wb * 256 + t;                  // j = n*64 + k
            int n = j >> 6, k = j & 63;
            g_WhT[j] = __float2half(W[k * 256 + n]);
        } else if (t < 192) {
            int pair = t >> 4, l = t & 15;         // pair = d*4 + h
            int d = pair >> 2, hh = pair & 3;
            float s = 0.0f;
#pragma unroll
            for (int q = 0; q < 4; q++)
                s += W_edge[d * 256 + hh * 64 + l + 16 * q] * att_edge[hh * 64 + l + 16 * q];
            s += __shfl_xor_sync(0xffffffffu, s, 8);
            s += __shfl_xor_sync(0xffffffffu, s, 4);
            s += __shfl_xor_sync(0xffffffffu, s, 2);
            s += __shfl_xor_sync(0xffffffffu, s, 1);
            if (l == 0) g_v[pair] = s;
        }
    }
}

// ====== K2: per-block inclusive scan (shuffle-based) ======
__global__ void __launch_bounds__(256) k_scan1() {
    __shared__ int ws[8];
    int b = blockIdx.x, t = threadIdx.x, lane = t & 31, w = t >> 5;
    int i = b * 256 + t;
    int x = (i < N_NODES) ? g_cnt[i] : 0;
#pragma unroll
    for (int o = 1; o < 32; o <<= 1) {
        int u = __shfl_up_sync(0xffffffffu, x, o);
        if (lane >= o) x += u;
    }
    if (lane == 31) ws[w] = x;
    __syncthreads();
    if (t < 8) {
        int y = ws[t];
#pragma unroll
        for (int o = 1; o < 8; o <<= 1) {
            int u = __shfl_up_sync(0x000000ffu, y, o);
            if (t >= o) y += u;
        }
        ws[t] = y;
    }
    __syncthreads();
    if (w) x += ws[w - 1];
    g_scan[i] = x;                       // inclusive within block
    if (t == 255) g_btot[b] = x;
}

// ====== K3: block offsets + write NodeRec.beg/cnt + reset g_cnt ======
__global__ void __launch_bounds__(256) k_scanB() {
    __shared__ int ws[8];
    int b = blockIdx.x, t = threadIdx.x, lane = t & 31, w = t >> 5;
    int v = (t < b) ? g_btot[t] : 0;
#pragma unroll
    for (int o = 16; o; o >>= 1) v += __shfl_xor_sync(0xffffffffu, v, o);
    if (lane == 0) ws[w] = v;
    __syncthreads();
    int boff = 0;
#pragma unroll
    for (int k = 0; k < 8; k++) boff += ws[k];
    int i = b * 256 + t;
    if (i < N_NODES) {
        int c = g_cnt[i];
        g_nd[i].beg = g_scan[i] - c + boff;       // exclusive prefix
        g_nd[i].cnt = c;
        g_cnt[i] = 0;                             // restore invariant for next replay
    }
}

// ---------------- tensor-core GEMM x = h @ W, fused a_src/a_dst ----------------
__device__ __forceinline__ void mma16816(float* c, unsigned a0, unsigned a1, unsigned a2,
                                         unsigned a3, unsigned b0, unsigned b1) {
    asm volatile(
        "mma.sync.aligned.m16n8k16.row.col.f32.f16.f16.f32 "
        "{%0,%1,%2,%3},{%4,%5,%6,%7},{%8,%9},{%0,%1,%2,%3};\n"
        : "+f"(c[0]), "+f"(c[1]), "+f"(c[2]), "+f"(c[3])
        : "r"(a0), "r"(a1), "r"(a2), "r"(a3), "r"(b0), "r"(b1));
}

__device__ __forceinline__ void ldsm4(unsigned& r0, unsigned& r1, unsigned& r2, unsigned& r3,
                                      unsigned saddr) {
    asm volatile("ldmatrix.sync.aligned.m8n8.x4.shared.b16 {%0,%1,%2,%3}, [%4];"
                 : "=r"(r0), "=r"(r1), "=r"(r2), "=r"(r3) : "r"(saddr));
}

// 64 nodes/block; 8 warps: rt = w&3 (16-row tile), cg = w>>2 (128-col group = 2 heads)
__global__ void __launch_bounds__(256, 2) k_gemm(const float* __restrict__ h,
                                                 const float* __restrict__ att_src,
                                                 const float* __restrict__ att_dst) {
    __shared__ __half As[64 * 72];    // 9216 B
    __shared__ __half Ws[256 * 72];   // 36864 B; re-used as store-stage after mainloop
    int t = threadIdx.x, lane = t & 31, w = t >> 5;
    int n0 = blockIdx.x * 64;

#pragma unroll
    for (int q = 0; q < 8; q++) {
        int j = t + 256 * q;
        int n = j >> 3, c = j & 7;
        *(uint4*)&Ws[n * 72 + c * 8] = ((const uint4*)g_WhT)[j];
    }
#pragma unroll
    for (int q = 0; q < 4; q++) {
        int i = t + 256 * q;
        int r = i >> 4, c4 = (i & 15) * 4;
        int node = n0 + r;
        float4 hv = (node < N_NODES) ? *(const float4*)&h[node * 64 + c4]
                                     : make_float4(0.f, 0.f, 0.f, 0.f);
        __half2 p0 = __floats2half2_rn(hv.x, hv.y);
        __half2 p1 = __floats2half2_rn(hv.z, hv.w);
        uint2 pk = {*(unsigned*)&p0, *(unsigned*)&p1};
        *(uint2*)&As[r * 72 + c4] = pk;
    }
    __syncthreads();

    int rt = w & 3, cg = w >> 2;
    int rbase = rt * 16;
    int qr = lane >> 2, qc = lane & 3;

    unsigned as_base = (unsigned)__cvta_generic_to_shared(As);
    unsigned ws_base = (unsigned)__cvta_generic_to_shared(Ws);
    unsigned a_addr0 = as_base + ((rbase + (lane & 15)) * 72 + 8 * (lane >> 4)) * 2;
    unsigned b_lane_off = (((lane & 7) + 8 * ((lane >> 3) >> 1)) * 72 + 8 * ((lane >> 3) & 1)) * 2;

    float acc[16][4];
#pragma unroll
    for (int i = 0; i < 16; i++)
#pragma unroll
        for (int j = 0; j < 4; j++) acc[i][j] = 0.f;

#pragma unroll
    for (int ks = 0; ks < 4; ks++) {
        int kk = ks * 16;
        unsigned a0, a1, a2, a3;
        ldsm4(a0, a1, a2, a3, a_addr0 + kk * 2);
#pragma unroll
        for (int nf2 = 0; nf2 < 8; nf2++) {
            int n = cg * 128 + nf2 * 16;
            unsigned b0, b1, b2, b3;
            ldsm4(b0, b1, b2, b3, ws_base + n * 144 + b_lane_off + kk * 2);
            mma16816(acc[nf2 * 2],     a0, a1, a2, a3, b0, b1);
            mma16816(acc[nf2 * 2 + 1], a0, a1, a2, a3, b2, b3);
        }
    }
    __syncthreads();   // all warps done reading Ws — safe to overlay stage

    // ---- stage x (half2) into smem, pitch 132 words: bank = 4*qr+qc, conflict-free ----
    unsigned* stage = (unsigned*)Ws;   // 64 rows * 132 words = 33792 B <= 36864 B
    int node_lo = n0 + rbase + qr;
    int node_hi = node_lo + 8;
    float psA_lo = 0.f, psA_hi = 0.f, pdA_lo = 0.f, pdA_hi = 0.f;   // head cg*2
    float psB_lo = 0.f, psB_hi = 0.f, pdB_lo = 0.f, pdB_hi = 0.f;   // head cg*2+1
#pragma unroll
    for (int nf = 0; nf < 16; nf++) {
        int col = cg * 128 + nf * 8 + 2 * qc;
        float2 sv = *(const float2*)&att_src[col];
        float2 dv = *(const float2*)&att_dst[col];
        if (nf < 8) {
            psA_lo += acc[nf][0] * sv.x + acc[nf][1] * sv.y;
            psA_hi += acc[nf][2] * sv.x + acc[nf][3] * sv.y;
            pdA_lo += acc[nf][0] * dv.x + acc[nf][1] * dv.y;
            pdA_hi += acc[nf][2] * dv.x + acc[nf][3] * dv.y;
        } else {
            psB_lo += acc[nf][0] * sv.x + acc[nf][1] * sv.y;
            psB_hi += acc[nf][2] * sv.x + acc[nf][3] * sv.y;
            pdB_lo += acc[nf][0] * dv.x + acc[nf][1] * dv.y;
            pdB_hi += acc[nf][2] * dv.x + acc[nf][3] * dv.y;
        }
        int h2 = cg * 64 + nf * 4 + qc;   // half2 column index
        __half2 plo = __floats2half2_rn(acc[nf][0], acc[nf][1]);
        __half2 phi = __floats2half2_rn(acc[nf][2], acc[nf][3]);
        stage[(rbase + qr) * 132 + h2]     = *(unsigned*)&plo;
        stage[(rbase + qr + 8) * 132 + h2] = *(unsigned*)&phi;
    }
#pragma unroll
    for (int o = 1; o <= 2; o <<= 1) {
        psA_lo += __shfl_xor_sync(0xffffffffu, psA_lo, o);
        psA_hi += __shfl_xor_sync(0xffffffffu, psA_hi, o);
        pdA_lo += __shfl_xor_sync(0xffffffffu, pdA_lo, o);
        pdA_hi += __shfl_xor_sync(0xffffffffu, pdA_hi, o);
        psB_lo += __shfl_xor_sync(0xffffffffu, psB_lo, o);
        psB_hi += __shfl_xor_sync(0xffffffffu, psB_hi, o);
        pdB_lo += __shfl_xor_sync(0xffffffffu, pdB_lo, o);
        pdB_hi += __shfl_xor_sync(0xffffffffu, pdB_hi, o);
    }
    if (qc == 0) {
        int hA = cg * 2, hB = cg * 2 + 1;
        if (node_lo < N_NODES) {
            g_asrc[node_lo * 4 + hA] = psA_lo;
            g_asrc[node_lo * 4 + hB] = psB_lo;
            ((float*)&g_nd[node_lo].adst)[hA] = pdA_lo;
            ((float*)&g_nd[node_lo].adst)[hB] = pdB_lo;
        }
        if (node_hi < N_NODES) {
            g_asrc[node_hi * 4 + hA] = psA_hi;
            g_asrc[node_hi * 4 + hB] = psB_hi;
            ((float*)&g_nd[node_hi].adst)[hA] = pdA_hi;
            ((float*)&g_nd[node_hi].adst)[hB] = pdB_hi;
        }
    }
    __syncthreads();

    // ---- coalesced copy stage -> g_x2: 2048 uint4, 8 per thread ----
#pragma unroll
    for (int q = 0; q < 8; q++) {
        int idx = t + 256 * q;
        int r = idx >> 5;            // row 0..63
        int c4 = (idx & 31) * 4;     // word col, 16B aligned
        int node = n0 + r;
        if (node < N_NODES)
            ((uint4*)&g_x2[node * 128])[idx & 31] = *(uint4*)&stage[r * 132 + c4];
    }
}

// ---------------- scatter: store exp(leaky(logit)) directly (max-free softmax) ----------------
__global__ void k_scatter(const float* __restrict__ attr) {
    int e = blockIdx.x * blockDim.x + threadIdx.x;
    if (e >= N_EDGES) return;
    int s = g_src[e], d = g_dst[e];
    float4 ad = g_nd[d].adst;
    int pos = g_nd[d].beg + g_rank[e];        // same 32B sector as adst
    float a0 = attr[e * 3 + 0], a1 = attr[e * 3 + 1], a2 = attr[e * 3 + 2];
    float4 as = *(const float4*)&g_asrc[s * 4];
    float4 o;
    o.x = as.x + ad.x + a0 * g_v[0] + a1 * g_v[4] + a2 * g_v[8];
    o.y = as.y + ad.y + a0 * g_v[1] + a1 * g_v[5] + a2 * g_v[9];
    o.z = as.z + ad.z + a0 * g_v[2] + a1 * g_v[6] + a2 * g_v[10];
    o.w = as.w + ad.w + a0 * g_v[3] + a1 * g_v[7] + a2 * g_v[11];
    o.x = o.x > 0.f ? o.x : 0.2f * o.x;
    o.y = o.y > 0.f ? o.y : 0.2f * o.y;
    o.z = o.z > 0.f ? o.z : 0.2f * o.z;
    o.w = o.w > 0.f ? o.w : 0.2f * o.w;
    // logits are O(10) here; exp is far from overflow (clamp at 80 for safety)
    o.x = expf(fminf(o.x, 80.f));
    o.y = expf(fminf(o.y, 80.f));
    o.z = expf(fminf(o.z, 80.f));
    o.w = expf(fminf(o.w, 80.f));
    *(float4*)&g_salpha[pos * 4] = o;
    g_ssrc[pos] = s;
}

// ---------------- warp per node: 2-pass (sum + unrolled gather), LN + SiLU ----------------
__global__ void __launch_bounds__(256) k_node(float* __restrict__ out,
                                              const float* __restrict__ bias,
                                              const float* __restrict__ gamma,
                                              const float* __restrict__ beta) {
    int t = threadIdx.x, lane = t & 31, w = t >> 5;
    int n = blockIdx.x * 8 + w;
    int2 seg = *(const int2*)&g_nd[n].beg;
    int beg = seg.x, end = seg.x + seg.y;
    const float4* sal = (const float4*)g_salpha;

    // pass 1: sum of stored exp values per head
    float4 sm = {0.f, 0.f, 0.f, 0.f};
    for (int k = beg + lane; k < end; k += 32) {
        float4 a = sal[k];
        sm.x += a.x; sm.y += a.y; sm.z += a.z; sm.w += a.w;
    }
#pragma unroll
    for (int o = 16; o; o >>= 1) {
        sm.x += __shfl_xor_sync(0xffffffffu, sm.x, o);
        sm.y += __shfl_xor_sync(0xffffffffu, sm.y, o);
        sm.z += __shfl_xor_sync(0xffffffffu, sm.z, o);
        sm.w += __shfl_xor_sync(0xffffffffu, sm.w, o);
    }

    // per-lane head constants
    int hd = lane >> 3;
    float sh = (hd == 0) ? sm.x : (hd == 1) ? sm.y : (hd == 2) ? sm.z : sm.w;
    float ih = 0.25f / (sh + 1e-16f);

    // pass 2: weighted gather of fp16 x, unrolled x2 for MLP; normalize at end
    float acc[8];
#pragma unroll
    for (int i = 0; i < 8; i++) acc[i] = 0.f;
    const uint4* xv4 = (const uint4*)g_x2;
    int k = beg;
    for (; k + 2 <= end; k += 2) {
        float4 a0v = sal[k];
        float4 a1v = sal[k + 1];
        int s0 = g_ssrc[k], s1 = g_ssrc[k + 1];
        uint4 X0 = xv4[s0 * 32 + lane];
        uint4 X1 = xv4[s1 * 32 + lane];
        float w0 = (hd == 0) ? a0v.x : (hd == 1) ? a0v.y : (hd == 2) ? a0v.z : a0v.w;
        float w1 = (hd == 0) ? a1v.x : (hd == 1) ? a1v.y : (hd == 2) ? a1v.z : a1v.w;
        const __half2* h0 = (const __half2*)&X0;
        const __half2* h1 = (const __half2*)&X1;
#pragma unroll
        for (int i = 0; i < 4; i++) {
            float2 f0 = __half22float2(h0[i]);
            float2 f1 = __half22float2(h1[i]);
            acc[2 * i]     += w0 * f0.x + w1 * f1.x;
            acc[2 * i + 1] += w0 * f0.y + w1 * f1.y;
        }
    }
    if (k < end) {
        float4 a0v = sal[k];
        int s0 = g_ssrc[k];
        uint4 X0 = xv4[s0 * 32 + lane];
        float w0 = (hd == 0) ? a0v.x : (hd == 1) ? a0v.y : (hd == 2) ? a0v.z : a0v.w;
        const __half2* h0 = (const __half2*)&X0;
#pragma unroll
        for (int i = 0; i < 4; i++) {
            float2 f0 = __half22float2(h0[i]);
            acc[2 * i]     += w0 * f0.x;
            acc[2 * i + 1] += w0 * f0.y;
        }
    }
#pragma unroll
    for (int i = 0; i < 8; i++) {
        acc[i] *= ih;                    // normalize once, before cross-head fold
        acc[i] += __shfl_xor_sync(0xffffffffu, acc[i], 8);
        acc[i] += __shfl_xor_sync(0xffffffffu, acc[i], 16);
    }

    // LN + SiLU over 64 channels (lanes 0..7 write)
    int j = lane & 7;
    float4 b0 = ((const float4*)bias)[2 * j];
    float4 b1 = ((const float4*)bias)[2 * j + 1];
    float v[8] = {acc[0] + b0.x, acc[1] + b0.y, acc[2] + b0.z, acc[3] + b0.w,
                  acc[4] + b1.x, acc[5] + b1.y, acc[6] + b1.z, acc[7] + b1.w};
    float sum = 0.f, sq = 0.f;
#pragma unroll
    for (int i = 0; i < 8; i++) { sum += v[i]; sq += v[i] * v[i]; }
#pragma unroll
    for (int o = 4; o; o >>= 1) {
        sum += __shfl_xor_sync(0xffffffffu, sum, o);
        sq  += __shfl_xor_sync(0xffffffffu, sq, o);
    }
    float mu  = sum * (1.0f / 64.0f);
    float var = sq * (1.0f / 64.0f) - mu * mu;
    float inv = rsqrtf(var + 1e-5f);
    float4 g0 = ((const float4*)gamma)[2 * j];
    float4 g1 = ((const float4*)gamma)[2 * j + 1];
    float4 e0 = ((const float4*)beta)[2 * j];
    float4 e1 = ((const float4*)beta)[2 * j + 1];
    float gg[8] = {g0.x, g0.y, g0.z, g0.w, g1.x, g1.y, g1.z, g1.w};
    float ee[8] = {e0.x, e0.y, e0.z, e0.w, e1.x, e1.y, e1.z, e1.w};
    float y[8];
#pragma unroll
    for (int i = 0; i < 8; i++) {
        float yy = (v[i] - mu) * inv * gg[i] + ee[i];
        y[i] = yy / (1.0f + expf(-yy));
    }
    if (lane < 8) {
        float4 o0 = {y[0], y[1], y[2], y[3]};
        float4 o1 = {y[4], y[5], y[6], y[7]};
        ((float4*)out)[n * 16 + 2 * j]     = o0;
        ((float4*)out)[n * 16 + 2 * j + 1] = o1;
    }
}

extern "C" void kernel_launch(void* const* d_in, const int* in_sizes, int n_in,
                              void* d_out, int out_size) {
    // order: t, h, edge_index, edge_attr, W, att_src, att_dst,
    //        W_edge, att_edge, bias, ln_gamma, ln_beta
    const float* h        = (const float*)d_in[1];
    const void*  ei       = d_in[2];
    const float* attr     = (const float*)d_in[3];
    const float* W        = (const float*)d_in[4];
    const float* att_src  = (const float*)d_in[5];
    const float* att_dst  = (const float*)d_in[6];
    const float* W_edge   = (const float*)d_in[7];
    const float* att_edge = (const float*)d_in[8];
    const float* bias     = (const float*)d_in[9];
    const float* gamma    = (const float*)d_in[10];
    const float* beta     = (const float*)d_in[11];
    float* out = (float*)d_out;

    k_prep   <<<PREP_EDGE_BLOCKS + 65, 256>>>((const unsigned*)ei, W, W_edge, att_edge);
    k_scan1  <<<NB1, 256>>>();
    k_scanB  <<<NB1, 256>>>();
    k_gemm   <<<(N_NODES + 63) / 64, 256>>>(h, att_src, att_dst);
    k_scatter<<<(N_EDGES + 255) / 256, 256>>>(attr);
    k_node   <<<N_NODES / 8, 256>>>(out, bias, gamma, beta);
}

// round 16
// speedup vs baseline: 1.1505x; 1.0832x over previous
#include <cuda_runtime.h>
#include <cuda_fp16.h>

#define N_NODES 50000
#define N_EDGES 800000
#define NB1 196             // ceil(50000/256)
#define PREP_EDGE_BLOCKS 3125   // 800000/256 exactly

// packed per-destination-node record: one 32B sector serves scatter's whole need
struct __align__(32) NodeRec {
    float4 adst;   // a_dst per head
    int beg;       // segment start
    int cnt;       // segment length
    int pad0, pad1;
};

// ---------------- scratch (static device globals; no allocation) ----------------
__device__ __align__(16) int   g_src[N_EDGES];
__device__ __align__(16) int   g_dst[N_EDGES];
__device__ __align__(16) int   g_rank[N_EDGES];
__device__ int   g_cnt[N_NODES];            // invariant: all-zero at kernel_launch entry
__device__ int   g_scan[NB1 * 256];
__device__ int   g_btot[NB1];
__device__ NodeRec g_nd[N_NODES];
__device__ __align__(16) int     g_ssrc[N_EDGES];
__device__ __align__(16) float   g_salpha[N_EDGES * 4];    // exp(leaky(logit)) per head, 12.8 MB
__device__ __align__(16) __half2 g_x2[N_NODES * 128];      // x in fp16, 25.6 MB
__device__ __align__(16) float   g_asrc[N_NODES * 4];
__device__ __align__(16) __half  g_WhT[256 * 64];          // W transposed [n][k], fp16
__device__ float g_v[12];                                  // [edim*4 + head]

// ====== K1: prep (block-local dtype detect + unpack + hist/rank) + W convert + v_edge ======
__global__ void __launch_bounds__(256) k_prep(const unsigned* __restrict__ p,
                                              const float* __restrict__ W,
                                              const float* __restrict__ W_edge,
                                              const float* __restrict__ att_edge) {
    int b = blockIdx.x, t = threadIdx.x;
    if (b < PREP_EDGE_BLOCKS) {
        __shared__ unsigned wacc[8];
        __shared__ int s_is64;
        int e = b * 256 + t;                       // always < N_EDGES (exact tiling)
        unsigned acc = p[2 * e + 1];               // high word if int64
#pragma unroll
        for (int o = 16; o; o >>= 1) acc |= __shfl_xor_sync(0xffffffffu, acc, o);
        if ((t & 31) == 0) wacc[t >> 5] = acc;
        __syncthreads();
        if (t == 0) {
            unsigned a = 0;
#pragma unroll
            for (int i = 0; i < 8; i++) a |= wacc[i];
            s_is64 = (a == 0);
        }
        __syncthreads();
        int s, d;
        if (s_is64) {
            const long long* q = (const long long*)p;
            s = (int)q[e]; d = (int)q[N_EDGES + e];
        } else {
            const int* q = (const int*)p;
            s = q[e]; d = q[N_EDGES + e];
        }
        g_src[e] = s;
        g_dst[e] = d;
        g_rank[e] = atomicAdd(&g_cnt[d], 1);
    } else {
        int wb = b - PREP_EDGE_BLOCKS;
        if (wb < 64) {
            int j = wb * 256 + t;                  // j = n*64 + k
            int n = j >> 6, k = j & 63;
            g_WhT[j] = __float2half(W[k * 256 + n]);
        } else if (t < 192) {
            int pair = t >> 4, l = t & 15;         // pair = d*4 + h
            int d = pair >> 2, hh = pair & 3;
            float s = 0.0f;
#pragma unroll
            for (int q = 0; q < 4; q++)
                s += W_edge[d * 256 + hh * 64 + l + 16 * q] * att_edge[hh * 64 + l + 16 * q];
            s += __shfl_xor_sync(0xffffffffu, s, 8);
            s += __shfl_xor_sync(0xffffffffu, s, 4);
            s += __shfl_xor_sync(0xffffffffu, s, 2);
            s += __shfl_xor_sync(0xffffffffu, s, 1);
            if (l == 0) g_v[pair] = s;
        }
    }
}

// ====== K2: per-block inclusive scan (shuffle-based) ======
__global__ void __launch_bounds__(256) k_scan1() {
    __shared__ int ws[8];
    int b = blockIdx.x, t = threadIdx.x, lane = t & 31, w = t >> 5;
    int i = b * 256 + t;
    int x = (i < N_NODES) ? g_cnt[i] : 0;
#pragma unroll
    for (int o = 1; o < 32; o <<= 1) {
        int u = __shfl_up_sync(0xffffffffu, x, o);
        if (lane >= o) x += u;
    }
    if (lane == 31) ws[w] = x;
    __syncthreads();
    if (t < 8) {
        int y = ws[t];
#pragma unroll
        for (int o = 1; o < 8; o <<= 1) {
            int u = __shfl_up_sync(0x000000ffu, y, o);
            if (t >= o) y += u;
        }
        ws[t] = y;
    }
    __syncthreads();
    if (w) x += ws[w - 1];
    g_scan[i] = x;                       // inclusive within block
    if (t == 255) g_btot[b] = x;
}

// ====== K3: block offsets + write NodeRec.beg/cnt + reset g_cnt ======
__global__ void __launch_bounds__(256) k_scanB() {
    __shared__ int ws[8];
    int b = blockIdx.x, t = threadIdx.x, lane = t & 31, w = t >> 5;
    int v = (t < b) ? g_btot[t] : 0;
#pragma unroll
    for (int o = 16; o; o >>= 1) v += __shfl_xor_sync(0xffffffffu, v, o);
    if (lane == 0) ws[w] = v;
    __syncthreads();
    int boff = 0;
#pragma unroll
    for (int k = 0; k < 8; k++) boff += ws[k];
    int i = b * 256 + t;
    if (i < N_NODES) {
        int c = g_cnt[i];
        g_nd[i].beg = g_scan[i] - c + boff;       // exclusive prefix
        g_nd[i].cnt = c;
        g_cnt[i] = 0;                             // restore invariant for next replay
    }
}

// ---------------- tensor-core GEMM x = h @ W, fused a_src/a_dst ----------------
__device__ __forceinline__ void mma16816(float* c, unsigned a0, unsigned a1, unsigned a2,
                                         unsigned a3, unsigned b0, unsigned b1) {
    asm volatile(
        "mma.sync.aligned.m16n8k16.row.col.f32.f16.f16.f32 "
        "{%0,%1,%2,%3},{%4,%5,%6,%7},{%8,%9},{%0,%1,%2,%3};\n"
        : "+f"(c[0]), "+f"(c[1]), "+f"(c[2]), "+f"(c[3])
        : "r"(a0), "r"(a1), "r"(a2), "r"(a3), "r"(b0), "r"(b1));
}

__device__ __forceinline__ void ldsm4(unsigned& r0, unsigned& r1, unsigned& r2, unsigned& r3,
                                      unsigned saddr) {
    asm volatile("ldmatrix.sync.aligned.m8n8.x4.shared.b16 {%0,%1,%2,%3}, [%4];"
                 : "=r"(r0), "=r"(r1), "=r"(r2), "=r"(r3) : "r"(saddr));
}

// 64 nodes/block; 8 warps: rt = w&3 (16-row tile), cg = w>>2 (128-col group = 2 heads)
__global__ void __launch_bounds__(256, 2) k_gemm(const float* __restrict__ h,
                                                 const float* __restrict__ att_src,
                                                 const float* __restrict__ att_dst) {
    __shared__ __half As[64 * 72];    // 9216 B
    __shared__ __half Ws[256 * 72];   // 36864 B; re-used as store-stage after mainloop
    int t = threadIdx.x, lane = t & 31, w = t >> 5;
    int n0 = blockIdx.x * 64;

#pragma unroll
    for (int q = 0; q < 8; q++) {
        int j = t + 256 * q;
        int n = j >> 3, c = j & 7;
        *(uint4*)&Ws[n * 72 + c * 8] = ((const uint4*)g_WhT)[j];
    }
#pragma unroll
    for (int q = 0; q < 4; q++) {
        int i = t + 256 * q;
        int r = i >> 4, c4 = (i & 15) * 4;
        int node = n0 + r;
        float4 hv = (node < N_NODES) ? *(const float4*)&h[node * 64 + c4]
                                     : make_float4(0.f, 0.f, 0.f, 0.f);
        __half2 p0 = __floats2half2_rn(hv.x, hv.y);
        __half2 p1 = __floats2half2_rn(hv.z, hv.w);
        uint2 pk = {*(unsigned*)&p0, *(unsigned*)&p1};
        *(uint2*)&As[r * 72 + c4] = pk;
    }
    __syncthreads();

    int rt = w & 3, cg = w >> 2;
    int rbase = rt * 16;
    int qr = lane >> 2, qc = lane & 3;

    unsigned as_base = (unsigned)__cvta_generic_to_shared(As);
    unsigned ws_base = (unsigned)__cvta_generic_to_shared(Ws);
    unsigned a_addr0 = as_base + ((rbase + (lane & 15)) * 72 + 8 * (lane >> 4)) * 2;
    unsigned b_lane_off = (((lane & 7) + 8 * ((lane >> 3) >> 1)) * 72 + 8 * ((lane >> 3) & 1)) * 2;

    float acc[16][4];
#pragma unroll
    for (int i = 0; i < 16; i++)
#pragma unroll
        for (int j = 0; j < 4; j++) acc[i][j] = 0.f;

#pragma unroll
    for (int ks = 0; ks < 4; ks++) {
        int kk = ks * 16;
        unsigned a0, a1, a2, a3;
        ldsm4(a0, a1, a2, a3, a_addr0 + kk * 2);
#pragma unroll
        for (int nf2 = 0; nf2 < 8; nf2++) {
            int n = cg * 128 + nf2 * 16;
            unsigned b0, b1, b2, b3;
            ldsm4(b0, b1, b2, b3, ws_base + n * 144 + b_lane_off + kk * 2);
            mma16816(acc[nf2 * 2],     a0, a1, a2, a3, b0, b1);
            mma16816(acc[nf2 * 2 + 1], a0, a1, a2, a3, b2, b3);
        }
    }
    __syncthreads();   // all warps done reading Ws — safe to overlay stage

    // ---- stage x (half2) into smem, pitch 132 words: bank = 4*qr+qc, conflict-free ----
    unsigned* stage = (unsigned*)Ws;   // 64 rows * 132 words = 33792 B <= 36864 B
    int node_lo = n0 + rbase + qr;
    int node_hi = node_lo + 8;
    float psA_lo = 0.f, psA_hi = 0.f, pdA_lo = 0.f, pdA_hi = 0.f;   // head cg*2
    float psB_lo = 0.f, psB_hi = 0.f, pdB_lo = 0.f, pdB_hi = 0.f;   // head cg*2+1
#pragma unroll
    for (int nf = 0; nf < 16; nf++) {
        int col = cg * 128 + nf * 8 + 2 * qc;
        float2 sv = *(const float2*)&att_src[col];
        float2 dv = *(const float2*)&att_dst[col];
        if (nf < 8) {
            psA_lo += acc[nf][0] * sv.x + acc[nf][1] * sv.y;
            psA_hi += acc[nf][2] * sv.x + acc[nf][3] * sv.y;
            pdA_lo += acc[nf][0] * dv.x + acc[nf][1] * dv.y;
            pdA_hi += acc[nf][2] * dv.x + acc[nf][3] * dv.y;
        } else {
            psB_lo += acc[nf][0] * sv.x + acc[nf][1] * sv.y;
            psB_hi += acc[nf][2] * sv.x + acc[nf][3] * sv.y;
            pdB_lo += acc[nf][0] * dv.x + acc[nf][1] * dv.y;
            pdB_hi += acc[nf][2] * dv.x + acc[nf][3] * dv.y;
        }
        int h2 = cg * 64 + nf * 4 + qc;   // half2 column index
        __half2 plo = __floats2half2_rn(acc[nf][0], acc[nf][1]);
        __half2 phi = __floats2half2_rn(acc[nf][2], acc[nf][3]);
        stage[(rbase + qr) * 132 + h2]     = *(unsigned*)&plo;
        stage[(rbase + qr + 8) * 132 + h2] = *(unsigned*)&phi;
    }
#pragma unroll
    for (int o = 1; o <= 2; o <<= 1) {
        psA_lo += __shfl_xor_sync(0xffffffffu, psA_lo, o);
        psA_hi += __shfl_xor_sync(0xffffffffu, psA_hi, o);
        pdA_lo += __shfl_xor_sync(0xffffffffu, pdA_lo, o);
        pdA_hi += __shfl_xor_sync(0xffffffffu, pdA_hi, o);
        psB_lo += __shfl_xor_sync(0xffffffffu, psB_lo, o);
        psB_hi += __shfl_xor_sync(0xffffffffu, psB_hi, o);
        pdB_lo += __shfl_xor_sync(0xffffffffu, pdB_lo, o);
        pdB_hi += __shfl_xor_sync(0xffffffffu, pdB_hi, o);
    }
    if (qc == 0) {
        int hA = cg * 2, hB = cg * 2 + 1;
        if (node_lo < N_NODES) {
            g_asrc[node_lo * 4 + hA] = psA_lo;
            g_asrc[node_lo * 4 + hB] = psB_lo;
            ((float*)&g_nd[node_lo].adst)[hA] = pdA_lo;
            ((float*)&g_nd[node_lo].adst)[hB] = pdB_lo;
        }
        if (node_hi < N_NODES) {
            g_asrc[node_hi * 4 + hA] = psA_hi;
            g_asrc[node_hi * 4 + hB] = psB_hi;
            ((float*)&g_nd[node_hi].adst)[hA] = pdA_hi;
            ((float*)&g_nd[node_hi].adst)[hB] = pdB_hi;
        }
    }
    __syncthreads();

    // ---- coalesced copy stage -> g_x2: 2048 uint4, 8 per thread ----
#pragma unroll
    for (int q = 0; q < 8; q++) {
        int idx = t + 256 * q;
        int r = idx >> 5;            // row 0..63
        int c4 = (idx & 31) * 4;     // word col, 16B aligned
        int node = n0 + r;
        if (node < N_NODES)
            ((uint4*)&g_x2[node * 128])[idx & 31] = *(uint4*)&stage[r * 132 + c4];
    }
}

// ---------------- scatter: store exp(leaky(logit)) directly (max-free softmax) ----------------
__global__ void k_scatter(const float* __restrict__ attr) {
    int e = blockIdx.x * blockDim.x + threadIdx.x;
    if (e >= N_EDGES) return;
    int s = g_src[e], d = g_dst[e];
    float4 ad = g_nd[d].adst;
    int pos = g_nd[d].beg + g_rank[e];        // same 32B sector as adst
    float a0 = attr[e * 3 + 0], a1 = attr[e * 3 + 1], a2 = attr[e * 3 + 2];
    float4 as = *(const float4*)&g_asrc[s * 4];
    float4 o;
    o.x = as.x + ad.x + a0 * g_v[0] + a1 * g_v[4] + a2 * g_v[8];
    o.y = as.y + ad.y + a0 * g_v[1] + a1 * g_v[5] + a2 * g_v[9];
    o.z = as.z + ad.z + a0 * g_v[2] + a1 * g_v[6] + a2 * g_v[10];
    o.w = as.w + ad.w + a0 * g_v[3] + a1 * g_v[7] + a2 * g_v[11];
    o.x = o.x > 0.f ? o.x : 0.2f * o.x;
    o.y = o.y > 0.f ? o.y : 0.2f * o.y;
    o.z = o.z > 0.f ? o.z : 0.2f * o.z;
    o.w = o.w > 0.f ? o.w : 0.2f * o.w;
    // logits are O(10) here; exp is far from overflow (clamp at 80 for safety)
    o.x = expf(fminf(o.x, 80.f));
    o.y = expf(fminf(o.y, 80.f));
    o.z = expf(fminf(o.z, 80.f));
    o.w = expf(fminf(o.w, 80.f));
    *(float4*)&g_salpha[pos * 4] = o;
    g_ssrc[pos] = s;
}

// ---------------- warp per node: 2-pass (sum + x4-unrolled gather), LN + SiLU ----------------
__global__ void __launch_bounds__(256) k_node(float* __restrict__ out,
                                              const float* __restrict__ bias,
                                              const float* __restrict__ gamma,
                                              const float* __restrict__ beta) {
    int t = threadIdx.x, lane = t & 31, w = t >> 5;
    int n = blockIdx.x * 8 + w;
    int2 seg = *(const int2*)&g_nd[n].beg;
    int beg = seg.x, end = seg.x + seg.y;
    const float4* sal = (const float4*)g_salpha;

    // pass 1: sum of stored exp values per head
    float4 sm = {0.f, 0.f, 0.f, 0.f};
    for (int k = beg + lane; k < end; k += 32) {
        float4 a = sal[k];
        sm.x += a.x; sm.y += a.y; sm.z += a.z; sm.w += a.w;
    }
#pragma unroll
    for (int o = 16; o; o >>= 1) {
        sm.x += __shfl_xor_sync(0xffffffffu, sm.x, o);
        sm.y += __shfl_xor_sync(0xffffffffu, sm.y, o);
        sm.z += __shfl_xor_sync(0xffffffffu, sm.z, o);
        sm.w += __shfl_xor_sync(0xffffffffu, sm.w, o);
    }

    // per-lane head constants
    int hd = lane >> 3;
    float sh = (hd == 0) ? sm.x : (hd == 1) ? sm.y : (hd == 2) ? sm.z : sm.w;
    float ih = 0.25f / (sh + 1e-16f);

    // pass 2: weighted gather of fp16 x, unrolled x4 for MLP; normalize at end
    float acc[8];
#pragma unroll
    for (int i = 0; i < 8; i++) acc[i] = 0.f;
    const uint4* xv4 = (const uint4*)g_x2;
    int k = beg;
    for (; k + 4 <= end; k += 4) {
        float4 a0v = sal[k],     a1v = sal[k + 1];
        float4 a2v = sal[k + 2], a3v = sal[k + 3];
        int s0 = g_ssrc[k],     s1 = g_ssrc[k + 1];
        int s2 = g_ssrc[k + 2], s3 = g_ssrc[k + 3];
        uint4 X0 = xv4[s0 * 32 + lane];
        uint4 X1 = xv4[s1 * 32 + lane];
        uint4 X2 = xv4[s2 * 32 + lane];
        uint4 X3 = xv4[s3 * 32 + lane];
        float w0 = (hd == 0) ? a0v.x : (hd == 1) ? a0v.y : (hd == 2) ? a0v.z : a0v.w;
        float w1 = (hd == 0) ? a1v.x : (hd == 1) ? a1v.y : (hd == 2) ? a1v.z : a1v.w;
        float w2 = (hd == 0) ? a2v.x : (hd == 1) ? a2v.y : (hd == 2) ? a2v.z : a2v.w;
        float w3 = (hd == 0) ? a3v.x : (hd == 1) ? a3v.y : (hd == 2) ? a3v.z : a3v.w;
        const __half2* h0 = (const __half2*)&X0;
        const __half2* h1 = (const __half2*)&X1;
        const __half2* h2 = (const __half2*)&X2;
        const __half2* h3 = (const __half2*)&X3;
#pragma unroll
        for (int i = 0; i < 4; i++) {
            float2 f0 = __half22float2(h0[i]);
            float2 f1 = __half22float2(h1[i]);
            float2 f2 = __half22float2(h2[i]);
            float2 f3 = __half22float2(h3[i]);
            acc[2 * i]     += w0 * f0.x + w1 * f1.x + w2 * f2.x + w3 * f3.x;
            acc[2 * i + 1] += w0 * f0.y + w1 * f1.y + w2 * f2.y + w3 * f3.y;
        }
    }
    for (; k + 2 <= end; k += 2) {
        float4 a0v = sal[k];
        float4 a1v = sal[k + 1];
        int s0 = g_ssrc[k], s1 = g_ssrc[k + 1];
        uint4 X0 = xv4[s0 * 32 + lane];
        uint4 X1 = xv4[s1 * 32 + lane];
        float w0 = (hd == 0) ? a0v.x : (hd == 1) ? a0v.y : (hd == 2) ? a0v.z : a0v.w;
        float w1 = (hd == 0) ? a1v.x : (hd == 1) ? a1v.y : (hd == 2) ? a1v.z : a1v.w;
        const __half2* h0 = (const __half2*)&X0;
        const __half2* h1 = (const __half2*)&X1;
#pragma unroll
        for (int i = 0; i < 4; i++) {
            float2 f0 = __half22float2(h0[i]);
            float2 f1 = __half22float2(h1[i]);
            acc[2 * i]     += w0 * f0.x + w1 * f1.x;
            acc[2 * i + 1] += w0 * f0.y + w1 * f1.y;
        }
    }
    if (k < end) {
        float4 a0v = sal[k];
        int s0 = g_ssrc[k];
        uint4 X0 = xv4[s0 * 32 + lane];
        float w0 = (hd == 0) ? a0v.x : (hd == 1) ? a0v.y : (hd == 2) ? a0v.z : a0v.w;
        const __half2* h0 = (const __half2*)&X0;
#pragma unroll
        for (int i = 0; i < 4; i++) {
            float2 f0 = __half22float2(h0[i]);
            acc[2 * i]     += w0 * f0.x;
            acc[2 * i + 1] += w0 * f0.y;
        }
    }
#pragma unroll
    for (int i = 0; i < 8; i++) {
        acc[i] *= ih;                    // normalize once, before cross-head fold
        acc[i] += __shfl_xor_sync(0xffffffffu, acc[i], 8);
        acc[i] += __shfl_xor_sync(0xffffffffu, acc[i], 16);
    }

    // LN + SiLU over 64 channels (lanes 0..7 write)
    int j = lane & 7;
    float4 b0 = ((const float4*)bias)[2 * j];
    float4 b1 = ((const float4*)bias)[2 * j + 1];
    float v[8] = {acc[0] + b0.x, acc[1] + b0.y, acc[2] + b0.z, acc[3] + b0.w,
                  acc[4] + b1.x, acc[5] + b1.y, acc[6] + b1.z, acc[7] + b1.w};
    float sum = 0.f, sq = 0.f;
#pragma unroll
    for (int i = 0; i < 8; i++) { sum += v[i]; sq += v[i] * v[i]; }
#pragma unroll
    for (int o = 4; o; o >>= 1) {
        sum += __shfl_xor_sync(0xffffffffu, sum, o);
        sq  += __shfl_xor_sync(0xffffffffu, sq, o);
    }
    float mu  = sum * (1.0f / 64.0f);
    float var = sq * (1.0f / 64.0f) - mu * mu;
    float inv = rsqrtf(var + 1e-5f);
    float4 g0 = ((const float4*)gamma)[2 * j];
    float4 g1 = ((const float4*)gamma)[2 * j + 1];
    float4 e0 = ((const float4*)beta)[2 * j];
    float4 e1 = ((const float4*)beta)[2 * j + 1];
    float gg[8] = {g0.x, g0.y, g0.z, g0.w, g1.x, g1.y, g1.z, g1.w};
    float ee[8] = {e0.x, e0.y, e0.z, e0.w, e1.x, e1.y, e1.z, e1.w};
    float y[8];
#pragma unroll
    for (int i = 0; i < 8; i++) {
        float yy = (v[i] - mu) * inv * gg[i] + ee[i];
        y[i] = yy / (1.0f + expf(-yy));
    }
    if (lane < 8) {
        float4 o0 = {y[0], y[1], y[2], y[3]};
        float4 o1 = {y[4], y[5], y[6], y[7]};
        ((float4*)out)[n * 16 + 2 * j]     = o0;
        ((float4*)out)[n * 16 + 2 * j + 1] = o1;
    }
}

extern "C" void kernel_launch(void* const* d_in, const int* in_sizes, int n_in,
                              void* d_out, int out_size) {
    // order: t, h, edge_index, edge_attr, W, att_src, att_dst,
    //        W_edge, att_edge, bias, ln_gamma, ln_beta
    const float* h        = (const float*)d_in[1];
    const void*  ei       = d_in[2];
    const float* attr     = (const float*)d_in[3];
    const float* W        = (const float*)d_in[4];
    const float* att_src  = (const float*)d_in[5];
    const float* att_dst  = (const float*)d_in[6];
    const float* W_edge   = (const float*)d_in[7];
    const float* att_edge = (const float*)d_in[8];
    const float* bias     = (const float*)d_in[9];
    const float* gamma    = (const float*)d_in[10];
    const float* beta     = (const float*)d_in[11];
    float* out = (float*)d_out;

    k_prep   <<<PREP_EDGE_BLOCKS + 65, 256>>>((const unsigned*)ei, W, W_edge, att_edge);
    k_scan1  <<<NB1, 256>>>();
    k_scanB  <<<NB1, 256>>>();
    k_gemm   <<<(N_NODES + 63) / 64, 256>>>(h, att_src, att_dst);
    k_scatter<<<(N_EDGES + 255) / 256, 256>>>(attr);
    k_node   <<<N_NODES / 8, 256>>>(out, bias, gamma, beta);
}